// round 11
// baseline (speedup 1.0000x reference)
#include <cuda_runtime.h>
#include <cstdint>

#define NMAX 100000
#define EMAX 1200000
#define CAP  64   // in-degree capacity; Poisson(12) => P(deg>64) ~ 1e-30, safe

// Scratch (__device__ globals; no allocation allowed). Zero-initialized at load.
// Row NMAX of g_h/g_hb is a permanent ZERO row (never written): gather slots
// padded with sentinel offset NMAX*256 contribute exact zeros.
__device__ float g_h [(size_t)(NMAX + 1) * 64];
__device__ float g_hb[(size_t)(NMAX + 1) * 64];
__device__ int   g_bucket[(size_t)NMAX * CAP];
__device__ int   g_cnt[NMAX];
__device__ int   g_dhist[CAP + 1];   // degree histogram (re-zeroed in final_k)
__device__ int   g_dbase[CAP + 1];   // prefix offsets (rewritten by scan_k)
__device__ int   g_order[NMAX];      // degree-sorted node ids

__device__ __forceinline__ float group8_sum(float v) {
#pragma unroll
    for (int o = 4; o; o >>= 1) v += __shfl_xor_sync(0xffffffffu, v, o);
    return v;
}

// ---------------- bucket fill (4 edges/thread, vectorized) ----------------
__global__ __launch_bounds__(256) void fill_k(
    const int* __restrict__ src, const int* __restrict__ dst, int E)
{
    int t  = blockIdx.x * 256 + threadIdx.x;
    int e4 = t * 4;
    if (e4 + 3 < E) {
        int4 s4 = __ldg((const int4*)src + t);
        int4 d4 = __ldg((const int4*)dst + t);
        int ss[4] = { s4.x, s4.y, s4.z, s4.w };
        int dd[4] = { d4.x, d4.y, d4.z, d4.w };
#pragma unroll
        for (int i = 0; i < 4; i++) {
            int pos = atomicAdd(&g_cnt[dd[i]], 1);
            if (pos < CAP) g_bucket[(size_t)dd[i] * CAP + pos] = ss[i];
        }
    } else {
        for (int e = e4; e < E; e++) {
            int d = __ldg(dst + e), s = __ldg(src + e);
            int pos = atomicAdd(&g_cnt[d], 1);
            if (pos < CAP) g_bucket[(size_t)d * CAP + pos] = s;
        }
    }
}

// ---------------- degree sort: hist -> scan -> scatter --------------------
__global__ __launch_bounds__(256) void hist_k(int n)
{
    __shared__ int sh[CAP + 1];
    int tid = threadIdx.x;
    if (tid <= CAP) sh[tid] = 0;
    __syncthreads();
    int node = blockIdx.x * 256 + tid;
    if (node < n) atomicAdd(&sh[min(g_cnt[node], CAP)], 1);
    __syncthreads();
    if (tid <= CAP && sh[tid] > 0) atomicAdd(&g_dhist[tid], sh[tid]);
}

__global__ __launch_bounds__(128) void scan_k()
{
    __shared__ int sh[CAP + 1];
    int tid = threadIdx.x;
    if (tid <= CAP) sh[tid] = g_dhist[tid];
    __syncthreads();
    if (tid == 0) {                 // 65-entry serial exclusive prefix in smem
        int acc = 0;
        for (int i = 0; i <= CAP; i++) { int v = sh[i]; sh[i] = acc; acc += v; }
    }
    __syncthreads();
    if (tid <= CAP) g_dbase[tid] = sh[tid];
}

__global__ __launch_bounds__(256) void order_k(int n)
{
    __shared__ int hcnt[CAP + 1], hoff[CAP + 1];
    int tid = threadIdx.x;
    if (tid <= CAP) hcnt[tid] = 0;
    __syncthreads();
    int node = blockIdx.x * 256 + tid;
    int deg = -1, myidx = 0;
    if (node < n) {
        deg = min(g_cnt[node], CAP);
        myidx = atomicAdd(&hcnt[deg], 1);
    }
    __syncthreads();
    if (tid <= CAP && hcnt[tid] > 0) hoff[tid] = atomicAdd(&g_dbase[tid], hcnt[tid]);
    __syncthreads();
    if (deg >= 0) g_order[hoff[deg] + myidx] = node;
}

// ---------------- shared building blocks ----------------------------------
// Stage bucket rows for the warp's 4 (arbitrary) nodes into shared as BYTE
// OFFSETS (id<<8); pad tail [m, mwr) with the sentinel offset NMAX<<8.
__device__ __forceinline__ int stage_ids(
    int* __restrict__ ish, int node_g, int m, int mw, int lane)
{
    int g = lane >> 3, sub = lane & 7;
    int mwr = (mw + 3) & ~3;
#pragma unroll
    for (int it = 0; it < 2; it++) {
        int t = lane + it * 32;
        int nodei = t >> 4;               // 0..3
        int s4    = (t & 15) << 2;        // slot base 0,4,..,60
        int mi = __shfl_sync(0xffffffffu, m,      nodei << 3);
        int nv = __shfl_sync(0xffffffffu, node_g, nodei << 3);
        if (s4 < mi) {
            int4 v = __ldg((const int4*)(g_bucket + (size_t)nv * CAP) + (t & 15));
            v.x <<= 8; v.y <<= 8; v.z <<= 8; v.w <<= 8;   // pre-scale to bytes
            *(int4*)&ish[nodei * 68 + s4] = v;
        }
    }
    __syncwarp();
    for (int s = m + sub; s < mwr; s += 8) ish[g * 68 + s] = NMAX << 8;
    __syncwarp();
    return mwr;
}

// Guard-free gather-sum: lane `sub` owns channels [4s,4s+4) and [32+4s,32+4s+4).
// Offsets are pre-scaled bytes -> 1 add per address. Packed f32x2 adds.
__device__ __forceinline__ void gather_node(
    const float* __restrict__ hsrc, const int* __restrict__ ish,
    int g, int mwr, int sub,
    unsigned long long& ac0, unsigned long long& ac1,
    unsigned long long& ac2, unsigned long long& ac3)
{
    const char* hb = (const char*)hsrc + sub * 16;
    ac0 = ac1 = ac2 = ac3 = 0ull;
    for (int j = 0; j < mwr; j += 4) {
        int4 o4 = *(const int4*)&ish[g * 68 + j];    // broadcast LDS.128
        int off[4] = { o4.x, o4.y, o4.z, o4.w };
#pragma unroll
        for (int q = 0; q < 4; q++) {
            const char* p = hb + off[q];
            unsigned long long a, b, c, d;
            asm("ld.global.nc.v2.u64 {%0,%1}, [%2];" : "=l"(a), "=l"(b) : "l"(p));
            asm("ld.global.nc.v2.u64 {%0,%1}, [%2];" : "=l"(c), "=l"(d) : "l"(p + 128));
            asm("add.rn.f32x2 %0, %0, %1;" : "+l"(ac0) : "l"(a));
            asm("add.rn.f32x2 %0, %0, %1;" : "+l"(ac1) : "l"(b));
            asm("add.rn.f32x2 %0, %0, %1;" : "+l"(ac2) : "l"(c));
            asm("add.rn.f32x2 %0, %0, %1;" : "+l"(ac3) : "l"(d));
        }
    }
}

__device__ __forceinline__ float4 unpack2(unsigned long long a,
                                          unsigned long long b)
{
    float4 r;
    asm("mov.b64 {%0,%1}, %2;" : "=f"(r.x), "=f"(r.y) : "l"(a));
    asm("mov.b64 {%0,%1}, %2;" : "=f"(r.z), "=f"(r.w) : "l"(b));
    return r;
}

// Packed-FFMA2 GEMM epilogue; nodes may be arbitrary ids (valid iff >= 0).
__device__ __forceinline__ void gemm_store(
    const float2* __restrict__ Ws2, const float2* __restrict__ bsh,
    const float4* __restrict__ tsh_w, float* __restrict__ hout,
    const int* nd, int lane)
{
    float2 bb2 = bsh[lane];
    unsigned long long accA, accB, accC, accD;
    asm("mov.b64 %0, {%1,%1};" : "=l"(accA) : "f"(bb2.x));
    asm("mov.b64 %0, {%1,%1};" : "=l"(accC) : "f"(bb2.y));
    accB = accA;
    accD = accC;

    uint32_t tbase = (uint32_t)__cvta_generic_to_shared(tsh_w);
#pragma unroll
    for (int k = 0; k < 64; k++) {
        unsigned long long t01, t23, wxx, wyy;
        asm("ld.shared.v2.u64 {%0,%1}, [%2];"
            : "=l"(t01), "=l"(t23) : "r"(tbase + (k + (k >> 3)) * 16));
        float2 w = Ws2[k * 33 + lane];
        asm("mov.b64 %0, {%1,%1};" : "=l"(wxx) : "f"(w.x));
        asm("mov.b64 %0, {%1,%1};" : "=l"(wyy) : "f"(w.y));
        asm("fma.rn.f32x2 %0, %1, %2, %0;" : "+l"(accA) : "l"(t01), "l"(wxx));
        asm("fma.rn.f32x2 %0, %1, %2, %0;" : "+l"(accB) : "l"(t23), "l"(wxx));
        asm("fma.rn.f32x2 %0, %1, %2, %0;" : "+l"(accC) : "l"(t01), "l"(wyy));
        asm("fma.rn.f32x2 %0, %1, %2, %0;" : "+l"(accD) : "l"(t23), "l"(wyy));
    }

    float2 a0, a1, a2, a3;
    asm("mov.b64 {%0,%1}, %2;" : "=f"(a0.x), "=f"(a1.x) : "l"(accA));
    asm("mov.b64 {%0,%1}, %2;" : "=f"(a2.x), "=f"(a3.x) : "l"(accB));
    asm("mov.b64 {%0,%1}, %2;" : "=f"(a0.y), "=f"(a1.y) : "l"(accC));
    asm("mov.b64 {%0,%1}, %2;" : "=f"(a2.y), "=f"(a3.y) : "l"(accD));

    float2* ho = (float2*)hout;
    if (nd[0] >= 0) ho[(size_t)nd[0] * 32 + lane] = a0;
    if (nd[1] >= 0) ho[(size_t)nd[1] * 32 + lane] = a1;
    if (nd[2] >= 0) ho[(size_t)nd[2] * 32 + lane] = a2;
    if (nd[3] >= 0) ho[(size_t)nd[3] * 32 + lane] = a3;
}

__device__ __forceinline__ void store_tangent(
    float4* __restrict__ tsh_w, float pre, float4 ua, float4 ub,
    int g, int sub)
{
    float* tp = (float*)tsh_w;
    float ta[4] = { pre*ua.x, pre*ua.y, pre*ua.z, pre*ua.w };
    float tb[4] = { pre*ub.x, pre*ub.y, pre*ub.z, pre*ub.w };
#pragma unroll
    for (int i = 0; i < 4; i++) {
        int k = 4 * sub + i;
        tp[4 * k + 4 * (k >> 3) + g] = ta[i];
        k += 32;
        tp[4 * k + 4 * (k >> 3) + g] = tb[i];
    }
}

// ---------------- layer 0: logmap(emb) @ W1 + b1 -> g_h -------------------
__global__ __launch_bounds__(256) void layer0_k(
    const float* __restrict__ emb,
    const float* __restrict__ W, const float* __restrict__ b,
    const float* __restrict__ curv, int n)
{
    __shared__ float2 Ws2[64 * 33];
    __shared__ float2 bsh[32];
    __shared__ __align__(16) float4 tsh[8 * 72];

    int tid = threadIdx.x;
    float* Wf = (float*)Ws2;
    for (int idx = tid; idx < 64 * 64; idx += 256) {
        int j = idx >> 6, k = idx & 63;
        Wf[k * 66 + j] = W[idx];
    }
    if (tid < 32) bsh[tid] = ((const float2*)b)[tid];
    __syncthreads();

    int lane = tid & 31, wid = tid >> 5;
    int g = lane >> 3, sub = lane & 7;
    int n0 = ((int)blockIdx.x * 8 + wid) * 4;
    if (n0 >= n) return;
    int node = n0 + g;
    int ndc  = node < n ? node : n - 1;

    float sc = sqrtf(fabsf(curv[0]));

    const float4* x4 = (const float4*)emb + (size_t)ndc * 16;
    float4 ua = __ldg(x4 + sub);
    float4 ub = __ldg(x4 + 8 + sub);
    float d8 = group8_sum(ua.x*ua.x + ua.y*ua.y + ua.z*ua.z + ua.w*ua.w +
                          ub.x*ub.x + ub.y*ub.y + ub.z*ub.z + ub.w*ub.w);
    float nx  = fmaxf(sqrtf(d8), 1e-15f);
    float arg = fminf(sc * nx, 1.0f - 1e-7f);
    float pre = atanhf(arg) / (sc * nx);

    store_tangent(tsh + wid * 72, pre, ua, ub, g, sub);
    __syncwarp();
    int nd[4] = { n0 + 0 < n ? n0 + 0 : -1, n0 + 1 < n ? n0 + 1 : -1,
                  n0 + 2 < n ? n0 + 2 : -1, n0 + 3 < n ? n0 + 3 : -1 };
    gemm_store(Ws2, bsh, tsh + wid * 72, g_h, nd, lane);
}

// ---------------- layer 1 (degree-sorted): gather -> exp/log -> GEMM ------
__global__ __launch_bounds__(256) void layer1_k(
    const float* __restrict__ W, const float* __restrict__ b,
    const float* __restrict__ curv, int n)
{
    __shared__ float2 Ws2[64 * 33];
    __shared__ float2 bsh[32];
    __shared__ __align__(16) float4 tsh[8 * 72];
    __shared__ __align__(16) int    ish[8 * 272];

    int tid = threadIdx.x;
    float* Wf = (float*)Ws2;
    for (int idx = tid; idx < 64 * 64; idx += 256) {
        int j = idx >> 6, k = idx & 63;
        Wf[k * 66 + j] = W[idx];
    }
    if (tid < 32) bsh[tid] = ((const float2*)b)[tid];
    __syncthreads();

    int lane = tid & 31, wid = tid >> 5;
    int g = lane >> 3, sub = lane & 7;
    int r0 = ((int)blockIdx.x * 8 + wid) * 4;
    if (r0 >= n) return;
    int rank = r0 + g;
    int node = rank < n ? g_order[rank] : -1;     // sorted by degree

    float sc = sqrtf(fabsf(curv[0]));

    int deg = node >= 0 ? min(g_cnt[node], CAP) : 0;
    int mw  = __reduce_max_sync(0xffffffffu, deg);
    int mwr = stage_ids(ish + wid * 272, node, deg, mw, lane);

    unsigned long long ac0, ac1, ac2, ac3;
    gather_node(g_h, ish + wid * 272, g, mwr, sub, ac0, ac1, ac2, ac3);
    float4 ua = unpack2(ac0, ac1);
    float4 ub = unpack2(ac2, ac3);

    float inv = deg > 0 ? 1.f / (float)deg : 0.f;
    float d8  = group8_sum(ua.x*ua.x + ua.y*ua.y + ua.z*ua.z + ua.w*ua.w +
                           ub.x*ub.x + ub.y*ub.y + ub.z*ub.z + ub.w*ub.w);
    float r   = sqrtf(d8);
    float un  = fmaxf(r * inv, 1e-15f);
    float fe  = tanhf(sc * un) / (sc * un);
    float pre = inv * fe;
    float nx  = fmaxf(r * pre, 1e-15f);
    float arg = fminf(sc * nx, 1.0f - 1e-7f);
    pre *= atanhf(arg) / (sc * nx);

    store_tangent(tsh + wid * 72, pre, ua, ub, g, sub);
    __syncwarp();
    int nd[4];
#pragma unroll
    for (int i = 0; i < 4; i++)
        nd[i] = (r0 + i < n) ? g_order[r0 + i] : -1;
    gemm_store(Ws2, bsh, tsh + wid * 72, g_hb, nd, lane);
}

// ---------------- final (degree-sorted): gather -> expmap -> out ----------
// Also resets g_cnt per node and g_dhist (block 0) for the next graph replay.
__global__ __launch_bounds__(256) void final_k(
    const float* __restrict__ curv, float* __restrict__ out, int n)
{
    __shared__ __align__(16) int ish[8 * 272];

    int tid = threadIdx.x, lane = tid & 31, wid = tid >> 5;
    if (blockIdx.x == 0 && tid <= CAP) g_dhist[tid] = 0;
    int g = lane >> 3, sub = lane & 7;
    int r0 = ((int)blockIdx.x * 8 + wid) * 4;
    if (r0 >= n) return;
    int rank = r0 + g;
    int node = rank < n ? g_order[rank] : -1;

    float sc  = sqrtf(fabsf(curv[0]));
    int deg   = node >= 0 ? min(g_cnt[node], CAP) : 0;
    int mw    = __reduce_max_sync(0xffffffffu, deg);
    int mwr   = stage_ids(ish + wid * 272, node, deg, mw, lane);

    unsigned long long ac0, ac1, ac2, ac3;
    gather_node(g_hb, ish + wid * 272, g, mwr, sub, ac0, ac1, ac2, ac3);
    float4 ua = unpack2(ac0, ac1);
    float4 ub = unpack2(ac2, ac3);

    float inv = deg > 0 ? 1.f / (float)deg : 0.f;
    float d8  = group8_sum(ua.x*ua.x + ua.y*ua.y + ua.z*ua.z + ua.w*ua.w +
                           ub.x*ub.x + ub.y*ub.y + ub.z*ub.z + ub.w*ub.w);
    float un  = fmaxf(sqrtf(d8) * inv, 1e-15f);
    float fe  = tanhf(sc * un) / (sc * un);
    float s   = inv * fe;

    if (node >= 0) {
        float4* o4 = (float4*)out + (size_t)node * 16;
        o4[sub]     = make_float4(s*ua.x, s*ua.y, s*ua.z, s*ua.w);
        o4[8 + sub] = make_float4(s*ub.x, s*ub.y, s*ub.z, s*ub.w);
        if (sub == 0) g_cnt[node] = 0;   // leave zeroed for next replay
    }
}

extern "C" void kernel_launch(void* const* d_in, const int* in_sizes, int n_in,
                              void* d_out, int out_size)
{
    const int*   src  = (const int*)d_in[0];
    const int*   dst  = (const int*)d_in[1];
    const float* emb  = (const float*)d_in[2];
    const float* W1   = (const float*)d_in[3];
    const float* b1   = (const float*)d_in[4];
    const float* W2   = (const float*)d_in[5];
    const float* b2   = (const float*)d_in[6];
    const float* curv = (const float*)d_in[7];
    float* out = (float*)d_out;

    int E = in_sizes[0];
    int N = in_sizes[2] / 64;
    if (N > NMAX) N = NMAX;
    if (E > EMAX) E = EMAX;

    int fillBlocks = (E + 1023) / 1024;   // 4 edges per thread
    int nodeBlocks = (N + 31) / 32;       // 8 warps x 4 nodes
    int nBlocks256 = (N + 255) / 256;

    fill_k  <<<fillBlocks, 256>>>(src, dst, E);
    layer0_k<<<nodeBlocks, 256>>>(emb, W1, b1, curv, N);
    hist_k  <<<nBlocks256, 256>>>(N);
    scan_k  <<<1, 128>>>();
    order_k <<<nBlocks256, 256>>>(N);
    layer1_k<<<nodeBlocks, 256>>>(W2, b2, curv, N);
    final_k <<<nodeBlocks, 256>>>(curv, out, N);
}

// round 14
// speedup vs baseline: 1.0533x; 1.0533x over previous
#include <cuda_runtime.h>
#include <cstdint>

#define NMAX 100000
#define EMAX 1200000
#define CAP  64   // in-degree capacity; Poisson(12) => P(deg>64) ~ 1e-30, safe

// Scratch (__device__ globals; no allocation allowed). Zero-initialized at load.
// Row NMAX of g_h/g_hb is a permanent ZERO row (never written): gather slots
// padded with sentinel offset NMAX*256 contribute exact zeros.
__device__ float g_h [(size_t)(NMAX + 1) * 64];
__device__ float g_hb[(size_t)(NMAX + 1) * 64];
__device__ int   g_bucket[(size_t)NMAX * CAP];
__device__ int   g_cnt[NMAX];

__device__ __forceinline__ float group8_sum(float v) {
#pragma unroll
    for (int o = 4; o; o >>= 1) v += __shfl_xor_sync(0xffffffffu, v, o);
    return v;
}

// ---------------- bucket fill (4 edges/thread, vectorized) ----------------
__global__ __launch_bounds__(256) void fill_k(
    const int* __restrict__ src, const int* __restrict__ dst, int E)
{
    int t  = blockIdx.x * 256 + threadIdx.x;
    int e4 = t * 4;
    if (e4 + 3 < E) {
        int4 s4 = __ldg((const int4*)src + t);
        int4 d4 = __ldg((const int4*)dst + t);
        int ss[4] = { s4.x, s4.y, s4.z, s4.w };
        int dd[4] = { d4.x, d4.y, d4.z, d4.w };
#pragma unroll
        for (int i = 0; i < 4; i++) {
            int pos = atomicAdd(&g_cnt[dd[i]], 1);
            if (pos < CAP) g_bucket[(size_t)dd[i] * CAP + pos] = ss[i];
        }
    } else {
        for (int e = e4; e < E; e++) {
            int d = __ldg(dst + e), s = __ldg(src + e);
            int pos = atomicAdd(&g_cnt[d], 1);
            if (pos < CAP) g_bucket[(size_t)d * CAP + pos] = s;
        }
    }
}

// Block-local degree sort: warp 0 bitonic-sorts the block's 32 (deg, idx)
// pairs ascending by degree; skeys[r] = (deg<<8)|idx for rank r. Warps then
// take adjacent ranks -> warp-max trip count ~ per-node degree (kills the
// E[max-of-4-Poisson] padding waste) at zero launch cost.
__device__ __forceinline__ void block_degsort(
    int* __restrict__ skeys, int n0b, int n, int lane, int wid)
{
    if (wid == 0) {
        int node = n0b + lane;
        int deg  = (node < n) ? min(g_cnt[node], CAP) : 0;
        unsigned key = ((unsigned)deg << 8) | (unsigned)lane;
#pragma unroll
        for (int k = 2; k <= 32; k <<= 1) {
#pragma unroll
            for (int j = k >> 1; j > 0; j >>= 1) {
                unsigned o = __shfl_xor_sync(0xffffffffu, key, j);
                bool dir   = ((lane & k) == 0);
                bool lower = ((lane & j) == 0);
                unsigned mn = min(key, o), mx = max(key, o);
                key = (dir == lower) ? mn : mx;
            }
        }
        skeys[lane] = (int)key;
    }
    __syncthreads();
}

// Stage bucket rows for the warp's 4 (arbitrary) nodes into shared as BYTE
// OFFSETS (id<<8); pad tail [m, mwr) with the sentinel offset NMAX<<8.
__device__ __forceinline__ int stage_ids(
    int* __restrict__ ish, int node_g, int m, int mw, int lane)
{
    int g = lane >> 3, sub = lane & 7;
    int mwr = (mw + 3) & ~3;
#pragma unroll
    for (int it = 0; it < 2; it++) {
        int t = lane + it * 32;
        int nodei = t >> 4;               // 0..3
        int s4    = (t & 15) << 2;        // slot base 0,4,..,60
        int mi = __shfl_sync(0xffffffffu, m,      nodei << 3);
        int nv = __shfl_sync(0xffffffffu, node_g, nodei << 3);
        if (s4 < mi) {
            int4 v = __ldg((const int4*)(g_bucket + (size_t)nv * CAP) + (t & 15));
            v.x <<= 8; v.y <<= 8; v.z <<= 8; v.w <<= 8;   // pre-scale to bytes
            *(int4*)&ish[nodei * 68 + s4] = v;
        }
    }
    __syncwarp();
    for (int s = m + sub; s < mwr; s += 8) ish[g * 68 + s] = NMAX << 8;
    __syncwarp();
    return mwr;
}

// Guard-free gather-sum: lane `sub` owns channels [4s,4s+4) and [32+4s,32+4s+4)
// (contiguous 128B half-rows). Offsets are pre-scaled bytes. Packed f32x2 adds.
__device__ __forceinline__ void gather_node(
    const float* __restrict__ hsrc, const int* __restrict__ ish,
    int g, int mwr, int sub,
    unsigned long long& ac0, unsigned long long& ac1,
    unsigned long long& ac2, unsigned long long& ac3)
{
    const char* hb = (const char*)hsrc + sub * 16;
    ac0 = ac1 = ac2 = ac3 = 0ull;
    for (int j = 0; j < mwr; j += 4) {
        int4 o4 = *(const int4*)&ish[g * 68 + j];    // broadcast LDS.128
        int off[4] = { o4.x, o4.y, o4.z, o4.w };
#pragma unroll
        for (int q = 0; q < 4; q++) {
            const char* p = hb + off[q];
            unsigned long long a, b, c, d;
            asm("ld.global.nc.v2.u64 {%0,%1}, [%2];" : "=l"(a), "=l"(b) : "l"(p));
            asm("ld.global.nc.v2.u64 {%0,%1}, [%2];" : "=l"(c), "=l"(d) : "l"(p + 128));
            asm("add.rn.f32x2 %0, %0, %1;" : "+l"(ac0) : "l"(a));
            asm("add.rn.f32x2 %0, %0, %1;" : "+l"(ac1) : "l"(b));
            asm("add.rn.f32x2 %0, %0, %1;" : "+l"(ac2) : "l"(c));
            asm("add.rn.f32x2 %0, %0, %1;" : "+l"(ac3) : "l"(d));
        }
    }
}

__device__ __forceinline__ float4 unpack2(unsigned long long a,
                                          unsigned long long b)
{
    float4 r;
    asm("mov.b64 {%0,%1}, %2;" : "=f"(r.x), "=f"(r.y) : "l"(a));
    asm("mov.b64 {%0,%1}, %2;" : "=f"(r.z), "=f"(r.w) : "l"(b));
    return r;
}

// Packed-FFMA2 GEMM epilogue; nodes may be arbitrary ids (valid iff >= 0).
__device__ __forceinline__ void gemm_store(
    const float2* __restrict__ Ws2, const float2* __restrict__ bsh,
    const float4* __restrict__ tsh_w, float* __restrict__ hout,
    const int* nd, int lane)
{
    float2 bb2 = bsh[lane];
    unsigned long long accA, accB, accC, accD;
    asm("mov.b64 %0, {%1,%1};" : "=l"(accA) : "f"(bb2.x));
    asm("mov.b64 %0, {%1,%1};" : "=l"(accC) : "f"(bb2.y));
    accB = accA;
    accD = accC;

    uint32_t tbase = (uint32_t)__cvta_generic_to_shared(tsh_w);
#pragma unroll
    for (int k = 0; k < 64; k++) {
        unsigned long long t01, t23, wxx, wyy;
        asm("ld.shared.v2.u64 {%0,%1}, [%2];"
            : "=l"(t01), "=l"(t23) : "r"(tbase + (k + (k >> 3)) * 16));
        float2 w = Ws2[k * 33 + lane];               // conflict-free LDS.64
        asm("mov.b64 %0, {%1,%1};" : "=l"(wxx) : "f"(w.x));
        asm("mov.b64 %0, {%1,%1};" : "=l"(wyy) : "f"(w.y));
        asm("fma.rn.f32x2 %0, %1, %2, %0;" : "+l"(accA) : "l"(t01), "l"(wxx));
        asm("fma.rn.f32x2 %0, %1, %2, %0;" : "+l"(accB) : "l"(t23), "l"(wxx));
        asm("fma.rn.f32x2 %0, %1, %2, %0;" : "+l"(accC) : "l"(t01), "l"(wyy));
        asm("fma.rn.f32x2 %0, %1, %2, %0;" : "+l"(accD) : "l"(t23), "l"(wyy));
    }

    float2 a0, a1, a2, a3;
    asm("mov.b64 {%0,%1}, %2;" : "=f"(a0.x), "=f"(a1.x) : "l"(accA));
    asm("mov.b64 {%0,%1}, %2;" : "=f"(a2.x), "=f"(a3.x) : "l"(accB));
    asm("mov.b64 {%0,%1}, %2;" : "=f"(a0.y), "=f"(a1.y) : "l"(accC));
    asm("mov.b64 {%0,%1}, %2;" : "=f"(a2.y), "=f"(a3.y) : "l"(accD));

    float2* ho = (float2*)hout;
    if (nd[0] >= 0) ho[(size_t)nd[0] * 32 + lane] = a0;
    if (nd[1] >= 0) ho[(size_t)nd[1] * 32 + lane] = a1;
    if (nd[2] >= 0) ho[(size_t)nd[2] * 32 + lane] = a2;
    if (nd[3] >= 0) ho[(size_t)nd[3] * 32 + lane] = a3;
}

__device__ __forceinline__ void store_tangent(
    float4* __restrict__ tsh_w, float pre, float4 ua, float4 ub,
    int g, int sub)
{
    float* tp = (float*)tsh_w;
    float ta[4] = { pre*ua.x, pre*ua.y, pre*ua.z, pre*ua.w };
    float tb[4] = { pre*ub.x, pre*ub.y, pre*ub.z, pre*ub.w };
#pragma unroll
    for (int i = 0; i < 4; i++) {
        int k = 4 * sub + i;
        tp[4 * k + 4 * (k >> 3) + g] = ta[i];
        k += 32;
        tp[4 * k + 4 * (k >> 3) + g] = tb[i];
    }
}

// ---------------- layer 0: logmap(emb) @ W1 + b1 -> g_h -------------------
__global__ __launch_bounds__(256) void layer0_k(
    const float* __restrict__ emb,
    const float* __restrict__ W, const float* __restrict__ b,
    const float* __restrict__ curv, int n)
{
    __shared__ float2 Ws2[64 * 33];
    __shared__ float2 bsh[32];
    __shared__ __align__(16) float4 tsh[8 * 72];

    int tid = threadIdx.x;
    float* Wf = (float*)Ws2;
    for (int idx = tid; idx < 64 * 64; idx += 256) {
        int j = idx >> 6, k = idx & 63;
        Wf[k * 66 + j] = W[idx];
    }
    if (tid < 32) bsh[tid] = ((const float2*)b)[tid];
    __syncthreads();

    int lane = tid & 31, wid = tid >> 5;
    int g = lane >> 3, sub = lane & 7;
    int n0 = ((int)blockIdx.x * 8 + wid) * 4;
    if (n0 >= n) return;
    int node = n0 + g;
    int ndc  = node < n ? node : n - 1;

    float sc = sqrtf(fabsf(curv[0]));

    const float4* x4 = (const float4*)emb + (size_t)ndc * 16;
    float4 ua = __ldg(x4 + sub);
    float4 ub = __ldg(x4 + 8 + sub);
    float d8 = group8_sum(ua.x*ua.x + ua.y*ua.y + ua.z*ua.z + ua.w*ua.w +
                          ub.x*ub.x + ub.y*ub.y + ub.z*ub.z + ub.w*ub.w);
    float nx  = fmaxf(sqrtf(d8), 1e-15f);
    float arg = fminf(sc * nx, 1.0f - 1e-7f);
    float pre = atanhf(arg) / (sc * nx);

    store_tangent(tsh + wid * 72, pre, ua, ub, g, sub);
    __syncwarp();
    int nd[4] = { n0 + 0 < n ? n0 + 0 : -1, n0 + 1 < n ? n0 + 1 : -1,
                  n0 + 2 < n ? n0 + 2 : -1, n0 + 3 < n ? n0 + 3 : -1 };
    gemm_store(Ws2, bsh, tsh + wid * 72, g_h, nd, lane);
}

// -------- layer 1 (block-degsorted): gather -> exp/log -> GEMM ------------
__global__ __launch_bounds__(256) void layer1_k(
    const float* __restrict__ W, const float* __restrict__ b,
    const float* __restrict__ curv, int n)
{
    __shared__ float2 Ws2[64 * 33];
    __shared__ float2 bsh[32];
    __shared__ __align__(16) float4 tsh[8 * 72];
    __shared__ __align__(16) int    ish[8 * 272];
    __shared__ int skeys[32];

    int tid = threadIdx.x, lane = tid & 31, wid = tid >> 5;
    float* Wf = (float*)Ws2;
    for (int idx = tid; idx < 64 * 64; idx += 256) {
        int j = idx >> 6, k = idx & 63;
        Wf[k * 66 + j] = W[idx];
    }
    if (tid < 32) bsh[tid] = ((const float2*)b)[tid];
    __syncthreads();

    int g = lane >> 3, sub = lane & 7;
    int n0b = (int)blockIdx.x * 32;
    if (n0b >= n) return;

    block_degsort(skeys, n0b, n, lane, wid);   // includes __syncthreads

    int key  = skeys[wid * 4 + g];
    int node = n0b + (key & 0xff);
    int deg  = key >> 8;
    if (node >= n) { node = -1; deg = 0; }

    float sc = sqrtf(fabsf(curv[0]));

    int mw  = __reduce_max_sync(0xffffffffu, deg);
    int mwr = stage_ids(ish + wid * 272, node, deg, mw, lane);

    unsigned long long ac0, ac1, ac2, ac3;
    gather_node(g_h, ish + wid * 272, g, mwr, sub, ac0, ac1, ac2, ac3);
    float4 ua = unpack2(ac0, ac1);
    float4 ub = unpack2(ac2, ac3);

    float inv = deg > 0 ? 1.f / (float)deg : 0.f;
    float d8  = group8_sum(ua.x*ua.x + ua.y*ua.y + ua.z*ua.z + ua.w*ua.w +
                           ub.x*ub.x + ub.y*ub.y + ub.z*ub.z + ub.w*ub.w);
    float r   = sqrtf(d8);
    float un  = fmaxf(r * inv, 1e-15f);
    float fe  = tanhf(sc * un) / (sc * un);
    float pre = inv * fe;
    float nx  = fmaxf(r * pre, 1e-15f);
    float arg = fminf(sc * nx, 1.0f - 1e-7f);
    pre *= atanhf(arg) / (sc * nx);

    store_tangent(tsh + wid * 72, pre, ua, ub, g, sub);
    __syncwarp();
    int nd[4];
#pragma unroll
    for (int i = 0; i < 4; i++) {
        int kk = skeys[wid * 4 + i];
        int nv = n0b + (kk & 0xff);
        nd[i] = nv < n ? nv : -1;
    }
    gemm_store(Ws2, bsh, tsh + wid * 72, g_hb, nd, lane);
}

// ------- final (block-degsorted): gather -> expmap -> out; reset g_cnt ----
__global__ __launch_bounds__(256) void final_k(
    const float* __restrict__ curv, float* __restrict__ out, int n)
{
    __shared__ __align__(16) int ish[8 * 272];
    __shared__ int skeys[32];

    int tid = threadIdx.x, lane = tid & 31, wid = tid >> 5;
    int g = lane >> 3, sub = lane & 7;
    int n0b = (int)blockIdx.x * 32;
    if (n0b >= n) return;

    block_degsort(skeys, n0b, n, lane, wid);

    int key  = skeys[wid * 4 + g];
    int node = n0b + (key & 0xff);
    int deg  = key >> 8;
    if (node >= n) { node = -1; deg = 0; }

    float sc  = sqrtf(fabsf(curv[0]));
    int mw    = __reduce_max_sync(0xffffffffu, deg);
    int mwr   = stage_ids(ish + wid * 272, node, deg, mw, lane);

    unsigned long long ac0, ac1, ac2, ac3;
    gather_node(g_hb, ish + wid * 272, g, mwr, sub, ac0, ac1, ac2, ac3);
    float4 ua = unpack2(ac0, ac1);
    float4 ub = unpack2(ac2, ac3);

    float inv = deg > 0 ? 1.f / (float)deg : 0.f;
    float d8  = group8_sum(ua.x*ua.x + ua.y*ua.y + ua.z*ua.z + ua.w*ua.w +
                           ub.x*ub.x + ub.y*ub.y + ub.z*ub.z + ub.w*ub.w);
    float un  = fmaxf(sqrtf(d8) * inv, 1e-15f);
    float fe  = tanhf(sc * un) / (sc * un);
    float s   = inv * fe;

    if (node >= 0) {
        float4* o4 = (float4*)out + (size_t)node * 16;
        o4[sub]     = make_float4(s*ua.x, s*ua.y, s*ua.z, s*ua.w);
        o4[8 + sub] = make_float4(s*ub.x, s*ub.y, s*ub.z, s*ub.w);
        if (sub == 0) g_cnt[node] = 0;   // leave zeroed for next replay
    }
}

extern "C" void kernel_launch(void* const* d_in, const int* in_sizes, int n_in,
                              void* d_out, int out_size)
{
    const int*   src  = (const int*)d_in[0];
    const int*   dst  = (const int*)d_in[1];
    const float* emb  = (const float*)d_in[2];
    const float* W1   = (const float*)d_in[3];
    const float* b1   = (const float*)d_in[4];
    const float* W2   = (const float*)d_in[5];
    const float* b2   = (const float*)d_in[6];
    const float* curv = (const float*)d_in[7];
    float* out = (float*)d_out;

    int E = in_sizes[0];
    int N = in_sizes[2] / 64;
    if (N > NMAX) N = NMAX;
    if (E > EMAX) E = EMAX;

    int fillBlocks = (E + 1023) / 1024;   // 4 edges per thread
    int nodeBlocks = (N + 31) / 32;       // 8 warps x 4 nodes

    fill_k  <<<fillBlocks, 256>>>(src, dst, E);
    layer0_k<<<nodeBlocks, 256>>>(emb, W1, b1, curv, N);
    layer1_k<<<nodeBlocks, 256>>>(W2, b2, curv, N);
    final_k <<<nodeBlocks, 256>>>(curv, out, N);
}